// round 11
// baseline (speedup 1.0000x reference)
#include <cuda_runtime.h>
#include <cuda_fp16.h>
#include <cstdint>

// ---------------------------------------------------------------------------
// Problem constants (fixed shapes)
// ---------------------------------------------------------------------------
static constexpr int M = 4096;
static constexpr int K = 4096;
static constexpr int N = 11008;
static constexpr int NP = N / 8;        // packed qweight cols
// GEMM tiling: CTA 128x128, 8 warps (2M x 4N), warp tile 64x32, TKT=64
static constexpr int TM = 128;
static constexpr int TN = 128;
static constexpr int TKT = 64;          // K elems per tile
static constexpr int STAGES = 3;
static constexpr int NK = K / TKT;      // 64 iterations
static constexpr int TILES_M = M / TM;  // 32
static constexpr int TILES_N = N / TN;  // 86

// SMEM stage: A[128][72] halfs then B[128][72] halfs
// 72-half rows = 36-word stride: 8-row ldmatrix footprints tile all 32 banks.
static constexpr int RSTRIDE = 72;
static constexpr int A_BYTES = TM * RSTRIDE * 2;        // 18432
static constexpr int STAGE_BYTES = 2 * A_BYTES;         // 36864
static constexpr int SMEM_TOTAL = STAGES * STAGE_BYTES; // 110592 (x2 CTAs/SM)

// Fused prep kernel partition
static constexpr int XBLOCKS = (M * K / 4) / 256;       // 16384 convert blocks
static constexpr int DQ_NB = N / 64;                    // 172
static constexpr int DQ_KB = K / 128;                   // 32
static constexpr int PREP_BLOCKS = XBLOCKS + DQ_NB * DQ_KB;

// ---------------------------------------------------------------------------
// Scratch (no allocation allowed anywhere)
// ---------------------------------------------------------------------------
__device__ __align__(256) __half g_xh[(size_t)M * K];   // x fp16 [M,K]
__device__ __align__(256) __half g_wh[(size_t)N * K];   // W fp16 [N,K] K-major

// ---------------------------------------------------------------------------
// PTX helpers (sm_80-level: assembles on plain sm_100 target)
// ---------------------------------------------------------------------------
__device__ __forceinline__ uint32_t smem_u32(const void* p) {
    uint32_t a;
    asm("{ .reg .u64 t; cvta.to.shared.u64 t, %1; cvt.u32.u64 %0, t; }"
        : "=r"(a) : "l"(p));
    return a;
}

__device__ __forceinline__ void cp_async16(uint32_t dst, const void* src) {
    asm volatile("cp.async.cg.shared.global [%0], [%1], 16;\n"
                 :: "r"(dst), "l"(src));
}
#define CP_COMMIT() asm volatile("cp.async.commit_group;" ::: "memory")
#define CP_WAIT(n)  asm volatile("cp.async.wait_group %0;" :: "n"(n) : "memory")

__device__ __forceinline__ void ldsm_x4(uint32_t& r0, uint32_t& r1,
                                        uint32_t& r2, uint32_t& r3, uint32_t addr) {
    asm volatile("ldmatrix.sync.aligned.m8n8.x4.shared.b16 {%0,%1,%2,%3}, [%4];"
                 : "=r"(r0), "=r"(r1), "=r"(r2), "=r"(r3) : "r"(addr));
}

__device__ __forceinline__ void mma16816(float* c, const uint32_t* a,
                                         uint32_t b0, uint32_t b1) {
    asm volatile(
        "mma.sync.aligned.m16n8k16.row.col.f32.f16.f16.f32 "
        "{%0,%1,%2,%3}, {%4,%5,%6,%7}, {%8,%9}, {%0,%1,%2,%3};"
        : "+f"(c[0]), "+f"(c[1]), "+f"(c[2]), "+f"(c[3])
        : "r"(a[0]), "r"(a[1]), "r"(a[2]), "r"(a[3]), "r"(b0), "r"(b1));
}

// ---------------------------------------------------------------------------
// Kernel 1 (fused prep): blocks [0, XBLOCKS) convert x fp32->fp16;
// blocks [XBLOCKS, ...) AWQ-dequant + transpose W -> g_wh[N][K] fp16.
// Both halves are pure-memory-bound; fusing overlaps their HBM streams.
// ---------------------------------------------------------------------------
__global__ void __launch_bounds__(256) prep_kernel(const float* __restrict__ x,
                                                   const int* __restrict__ qw,
                                                   const float* __restrict__ scales,
                                                   const int* __restrict__ qz) {
    const int t = threadIdx.x;
    if (blockIdx.x < XBLOCKS) {
        // ---- convert x ----
        const size_t i = (size_t)blockIdx.x * 256 + t;
        float4 f = reinterpret_cast<const float4*>(x)[i];
        reinterpret_cast<__half2*>(g_xh)[2 * i + 0] = __floats2half2_rn(f.x, f.y);
        reinterpret_cast<__half2*>(g_xh)[2 * i + 1] = __floats2half2_rn(f.z, f.w);
        return;
    }
    // ---- dequant W ----
    __shared__ __half wt[64][136];
    __shared__ float ss[64];
    __shared__ int   zz[8];

    const int bx = blockIdx.x - XBLOCKS;
    const int nt = (bx % DQ_NB) * 64;
    const int g  = bx / DQ_NB;           // group index (GROUP == 128 == K-tile)
    const int kt = g * 128;
    const int c0 = nt >> 3;

    if (t < 8)  zz[t] = qz[(size_t)g * NP + c0 + t];
    if (t < 64) ss[t] = scales[(size_t)g * N + nt + t];
    __syncthreads();

    const int klp   = t & 63;            // k-pair: k = 2*klp, 2*klp+1
    const int cbase = t >> 6;            // 0..3

#pragma unroll
    for (int p = 0; p < 2; p++) {
        const int cl = cbase + 4 * p;    // packed col 0..7
        const int zp = zz[cl];
        const int q0 = qw[(size_t)(kt + 2 * klp)     * NP + c0 + cl];
        const int q1 = qw[(size_t)(kt + 2 * klp + 1) * NP + c0 + cl];
#pragma unroll
        for (int i = 0; i < 8; i++) {
            // AWQ nibble shifts: 4 * [0,4,1,5,2,6,3,7]
            const int sh = ((i & 1) ? 16 : 0) + (i >> 1) * 4;
            const float s = ss[cl * 8 + i];
            const float z = (float)((zp >> sh) & 0xF);
            const float w0 = ((float)((q0 >> sh) & 0xF) - z) * s;
            const float w1 = ((float)((q1 >> sh) & 0xF) - z) * s;
            *reinterpret_cast<__half2*>(&wt[cl * 8 + i][2 * klp]) =
                __floats2half2_rn(w0, w1);
        }
    }
    __syncthreads();

#pragma unroll
    for (int p = 0; p < 4; p++) {
        const int idx = p * 256 + t;
        const int row = idx >> 4, ch = idx & 15;
        const uint4 v = *reinterpret_cast<const uint4*>(&wt[row][ch * 8]);
        *reinterpret_cast<uint4*>(&g_wh[(size_t)(nt + row) * K + kt + ch * 8]) = v;
    }
}

// ---------------------------------------------------------------------------
// Kernel 2: HMMA GEMM  out[M,N] = x @ W^T + bias   (R9-proven config)
// CTA 128x128, 8 warps (2x4), warp tile 64x32, TKT=64, 3-stage cp.async,
// 2 CTAs/SM; prefetch issued BEFORE compute each iteration.
// ---------------------------------------------------------------------------
__global__ void __launch_bounds__(256, 2) awq_gemm_kernel(const float* __restrict__ bias,
                                                          float* __restrict__ out) {
    extern __shared__ char smem[];
    const uint32_t sb = smem_u32(smem);
    const int t = threadIdx.x, wid = t >> 5, lid = t & 31;
    const int bm = blockIdx.x % TILES_M;       // M fastest: wave shares B-tiles in L2
    const int bn = blockIdx.x / TILES_M;
    const int m0 = bm * TM, n0 = bn * TN;
    const int wm = wid & 1, wn = wid >> 1;     // warp grid 2 (M) x 4 (N)

    // Hoisted cp.async addressing: 256 threads cover 32 rows/pass (8 x 16B
    // chunks per 128B row), 4 passes per operand.
    const int lrow = t >> 3, lj = t & 7;
    const __half* gA = g_xh + (size_t)(m0 + lrow) * K + lj * 8;
    const __half* gB = g_wh + (size_t)(n0 + lrow) * K + lj * 8;
    const uint32_t so = lrow * (RSTRIDE * 2) + lj * 16;
    static constexpr size_t GSTRIDE32 = (size_t)32 * K;
    static constexpr uint32_t SSTRIDE32 = 32 * (RSTRIDE * 2);

    // ldmatrix lane addressing
    const int sel = lid >> 3, lr = lid & 7;
    const int a_moff = (sel & 1) * 8, a_koff = (sel >> 1) * 8;   // A: m0k0,m8k0,m0k8,m8k8
    const int b_koff = (sel & 1) * 8, b_noff = (sel >> 1) * 8;   // B: n0k0,n0k8,n8k0,n8k8

    float c[4][4][4];
#pragma unroll
    for (int i = 0; i < 4; i++)
#pragma unroll
        for (int j = 0; j < 4; j++)
#pragma unroll
            for (int q = 0; q < 4; q++) c[i][j][q] = 0.f;

    // Prologue: fill STAGES-1 stages
#pragma unroll
    for (int s = 0; s < STAGES - 1; s++) {
        const uint32_t a_s = sb + s * STAGE_BYTES;
        const uint32_t b_s = a_s + A_BYTES;
        const int ko = s * TKT;
#pragma unroll
        for (int p = 0; p < 4; p++) {
            cp_async16(a_s + so + p * SSTRIDE32, gA + p * GSTRIDE32 + ko);
            cp_async16(b_s + so + p * SSTRIDE32, gB + p * GSTRIDE32 + ko);
        }
        CP_COMMIT();
    }

    int st = 0, nst = STAGES - 1;     // avoid %3 in the loop
    for (int kc = 0; kc < NK; kc++) {
        CP_WAIT(STAGES - 2);
        __syncthreads();
        const uint32_t a_s = sb + st * STAGE_BYTES;
        const uint32_t b_s = a_s + A_BYTES;

        // Prefetch stage nst FIRST: its last reader was iteration kc-1,
        // ordered by the barrier above, so writing now is safe and gives
        // the loads an extra half-chunk of latency slack.
        const int nk = kc + STAGES - 1;
        if (nk < NK) {
            const uint32_t na_s = sb + nst * STAGE_BYTES;
            const uint32_t nb_s = na_s + A_BYTES;
            const int ko = nk * TKT;
#pragma unroll
            for (int p = 0; p < 4; p++) {
                cp_async16(na_s + so + p * SSTRIDE32, gA + p * GSTRIDE32 + ko);
                cp_async16(nb_s + so + p * SSTRIDE32, gB + p * GSTRIDE32 + ko);
            }
        }
        CP_COMMIT();

#pragma unroll
        for (int ks = 0; ks < 4; ks++) {
            const int kcol = ks * 16;
            uint32_t a[4][4], bb[2][4];
#pragma unroll
            for (int mf = 0; mf < 4; mf++) {
                const int arow = wm * 64 + mf * 16 + a_moff + lr;
                ldsm_x4(a[mf][0], a[mf][1], a[mf][2], a[mf][3],
                        a_s + (arow * RSTRIDE + kcol + a_koff) * 2);
            }
#pragma unroll
            for (int nf2 = 0; nf2 < 2; nf2++) {
                const int brow = wn * 32 + nf2 * 16 + b_noff + lr;
                ldsm_x4(bb[nf2][0], bb[nf2][1], bb[nf2][2], bb[nf2][3],
                        b_s + (brow * RSTRIDE + kcol + b_koff) * 2);
            }
#pragma unroll
            for (int mf = 0; mf < 4; mf++) {
#pragma unroll
                for (int nf = 0; nf < 4; nf++)
                    mma16816(c[mf][nf], a[mf],
                             bb[nf >> 1][(nf & 1) * 2], bb[nf >> 1][(nf & 1) * 2 + 1]);
            }
        }

        if (++st == STAGES) st = 0;
        if (++nst == STAGES) nst = 0;
    }

    // Epilogue: direct fp32 stores + bias
    const int qr = lid >> 2, qc = lid & 3;
#pragma unroll
    for (int mf = 0; mf < 4; mf++) {
        const int row = m0 + wm * 64 + mf * 16 + qr;
#pragma unroll
        for (int nf = 0; nf < 4; nf++) {
            const int col = n0 + wn * 32 + nf * 8 + qc * 2;
            const float2 b2 = *reinterpret_cast<const float2*>(bias + col);
            float2 v0 = make_float2(c[mf][nf][0] + b2.x, c[mf][nf][1] + b2.y);
            float2 v1 = make_float2(c[mf][nf][2] + b2.x, c[mf][nf][3] + b2.y);
            *reinterpret_cast<float2*>(out + (size_t)row * N + col) = v0;
            *reinterpret_cast<float2*>(out + (size_t)(row + 8) * N + col) = v1;
        }
    }
}

// ---------------------------------------------------------------------------
// Launch
// ---------------------------------------------------------------------------
extern "C" void kernel_launch(void* const* d_in, const int* in_sizes, int n_in,
                              void* d_out, int out_size) {
    (void)in_sizes; (void)n_in; (void)out_size;
    const float* x    = (const float*)d_in[0];
    const int*   qw   = (const int*)d_in[1];
    const float* sc   = (const float*)d_in[2];
    const int*   qz   = (const int*)d_in[3];
    const float* bias = (const float*)d_in[4];
    float* out = (float*)d_out;

    prep_kernel<<<PREP_BLOCKS, 256>>>(x, qw, sc, qz);

    cudaFuncSetAttribute(awq_gemm_kernel,
                         cudaFuncAttributeMaxDynamicSharedMemorySize, SMEM_TOTAL);
    awq_gemm_kernel<<<TILES_M * TILES_N, 256, SMEM_TOTAL>>>(bias, out);
}

// round 12
// speedup vs baseline: 1.1299x; 1.1299x over previous
#include <cuda_runtime.h>
#include <cuda_fp16.h>
#include <cstdint>

// ---------------------------------------------------------------------------
// Problem constants (fixed shapes)
// ---------------------------------------------------------------------------
static constexpr int M = 4096;
static constexpr int K = 4096;
static constexpr int N = 11008;
static constexpr int NP = N / 8;        // packed qweight cols
// GEMM tiling: CTA 128x128, 8 warps (2M x 4N), warp tile 64x32, TKT=64
static constexpr int TM = 128;
static constexpr int TN = 128;
static constexpr int TKT = 64;          // K elems per tile
static constexpr int STAGES = 3;
static constexpr int NK = K / TKT;      // 64 iterations
static constexpr int TILES_M = M / TM;  // 32
static constexpr int TILES_N = N / TN;  // 86

// SMEM stage: A[128][72] halfs then B[128][72] halfs
// 72-half rows = 36-word stride: 8-row ldmatrix footprints tile all 32 banks.
static constexpr int RSTRIDE = 72;
static constexpr int A_BYTES = TM * RSTRIDE * 2;        // 18432
static constexpr int STAGE_BYTES = 2 * A_BYTES;         // 36864
static constexpr int SMEM_TOTAL = STAGES * STAGE_BYTES; // 110592 (x2 CTAs/SM)

// Fused prep kernel partition
static constexpr int XBLOCKS = (M * K / 4) / 256;       // 16384 convert blocks
static constexpr int DQ_NB = N / 64;                    // 172
static constexpr int DQ_KB = K / 128;                   // 32
static constexpr int PREP_BLOCKS = XBLOCKS + DQ_NB * DQ_KB;

// ---------------------------------------------------------------------------
// Scratch (no allocation allowed anywhere)
// ---------------------------------------------------------------------------
__device__ __align__(256) __half g_xh[(size_t)M * K];   // x fp16 [M,K]
__device__ __align__(256) __half g_wh[(size_t)N * K];   // W fp16 [N,K] K-major

// ---------------------------------------------------------------------------
// PTX helpers (sm_80-level: assembles on plain sm_100 target)
// ---------------------------------------------------------------------------
__device__ __forceinline__ uint32_t smem_u32(const void* p) {
    uint32_t a;
    asm("{ .reg .u64 t; cvta.to.shared.u64 t, %1; cvt.u32.u64 %0, t; }"
        : "=r"(a) : "l"(p));
    return a;
}

__device__ __forceinline__ void cp_async16(uint32_t dst, const void* src) {
    asm volatile("cp.async.cg.shared.global [%0], [%1], 16;\n"
                 :: "r"(dst), "l"(src));
}
#define CP_COMMIT() asm volatile("cp.async.commit_group;" ::: "memory")
#define CP_WAIT(n)  asm volatile("cp.async.wait_group %0;" :: "n"(n) : "memory")

__device__ __forceinline__ void ldsm_x4(uint32_t& r0, uint32_t& r1,
                                        uint32_t& r2, uint32_t& r3, uint32_t addr) {
    asm volatile("ldmatrix.sync.aligned.m8n8.x4.shared.b16 {%0,%1,%2,%3}, [%4];"
                 : "=r"(r0), "=r"(r1), "=r"(r2), "=r"(r3) : "r"(addr));
}

__device__ __forceinline__ void mma16816(float* c, const uint32_t* a,
                                         uint32_t b0, uint32_t b1) {
    asm volatile(
        "mma.sync.aligned.m16n8k16.row.col.f32.f16.f16.f32 "
        "{%0,%1,%2,%3}, {%4,%5,%6,%7}, {%8,%9}, {%0,%1,%2,%3};"
        : "+f"(c[0]), "+f"(c[1]), "+f"(c[2]), "+f"(c[3])
        : "r"(a[0]), "r"(a[1]), "r"(a[2]), "r"(a[3]), "r"(b0), "r"(b1));
}

// ---------------------------------------------------------------------------
// Kernel 1 (fused prep): blocks [0, XBLOCKS) convert x fp32->fp16;
// blocks [XBLOCKS, ...) AWQ-dequant + transpose W -> g_wh[N][K] fp16.
// ---------------------------------------------------------------------------
__global__ void __launch_bounds__(256) prep_kernel(const float* __restrict__ x,
                                                   const int* __restrict__ qw,
                                                   const float* __restrict__ scales,
                                                   const int* __restrict__ qz) {
    const int t = threadIdx.x;
    if (blockIdx.x < XBLOCKS) {
        // ---- convert x ----
        const size_t i = (size_t)blockIdx.x * 256 + t;
        float4 f = reinterpret_cast<const float4*>(x)[i];
        reinterpret_cast<__half2*>(g_xh)[2 * i + 0] = __floats2half2_rn(f.x, f.y);
        reinterpret_cast<__half2*>(g_xh)[2 * i + 1] = __floats2half2_rn(f.z, f.w);
        return;
    }
    // ---- dequant W ----
    __shared__ __half wt[64][136];
    __shared__ float ss[64];
    __shared__ int   zz[8];

    const int bx = blockIdx.x - XBLOCKS;
    const int nt = (bx % DQ_NB) * 64;
    const int g  = bx / DQ_NB;           // group index (GROUP == 128 == K-tile)
    const int kt = g * 128;
    const int c0 = nt >> 3;

    if (t < 8)  zz[t] = qz[(size_t)g * NP + c0 + t];
    if (t < 64) ss[t] = scales[(size_t)g * N + nt + t];
    __syncthreads();

    const int klp   = t & 63;            // k-pair: k = 2*klp, 2*klp+1
    const int cbase = t >> 6;            // 0..3

#pragma unroll
    for (int p = 0; p < 2; p++) {
        const int cl = cbase + 4 * p;    // packed col 0..7
        const int zp = zz[cl];
        const int q0 = qw[(size_t)(kt + 2 * klp)     * NP + c0 + cl];
        const int q1 = qw[(size_t)(kt + 2 * klp + 1) * NP + c0 + cl];
#pragma unroll
        for (int i = 0; i < 8; i++) {
            // AWQ nibble shifts: 4 * [0,4,1,5,2,6,3,7]
            const int sh = ((i & 1) ? 16 : 0) + (i >> 1) * 4;
            const float s = ss[cl * 8 + i];
            const float z = (float)((zp >> sh) & 0xF);
            const float w0 = ((float)((q0 >> sh) & 0xF) - z) * s;
            const float w1 = ((float)((q1 >> sh) & 0xF) - z) * s;
            *reinterpret_cast<__half2*>(&wt[cl * 8 + i][2 * klp]) =
                __floats2half2_rn(w0, w1);
        }
    }
    __syncthreads();

#pragma unroll
    for (int p = 0; p < 4; p++) {
        const int idx = p * 256 + t;
        const int row = idx >> 4, ch = idx & 15;
        const uint4 v = *reinterpret_cast<const uint4*>(&wt[row][ch * 8]);
        *reinterpret_cast<uint4*>(&g_wh[(size_t)(nt + row) * K + kt + ch * 8]) = v;
    }
}

// ---------------------------------------------------------------------------
// Kernel 2: HMMA GEMM  out[M,N] = x @ W^T + bias
// EXACT R9 mainloop ordering: compute first, then next-stage loads, then
// commit. CTA 128x128, 8 warps (2x4), warp tile 64x32, TKT=64, 3 stages,
// 2 CTAs/SM.
// ---------------------------------------------------------------------------
__global__ void __launch_bounds__(256, 2) awq_gemm_kernel(const float* __restrict__ bias,
                                                          float* __restrict__ out) {
    extern __shared__ char smem[];
    const uint32_t sb = smem_u32(smem);
    const int t = threadIdx.x, wid = t >> 5, lid = t & 31;
    const int bm = blockIdx.x % TILES_M;       // M fastest: wave shares B-tiles in L2
    const int bn = blockIdx.x / TILES_M;
    const int m0 = bm * TM, n0 = bn * TN;
    const int wm = wid & 1, wn = wid >> 1;     // warp grid 2 (M) x 4 (N)

    // Hoisted cp.async addressing: 256 threads cover 32 rows/pass (8 x 16B
    // chunks per 128B row), 4 passes per operand.
    const int lrow = t >> 3, lj = t & 7;
    const __half* gA = g_xh + (size_t)(m0 + lrow) * K + lj * 8;
    const __half* gB = g_wh + (size_t)(n0 + lrow) * K + lj * 8;
    const uint32_t so = lrow * (RSTRIDE * 2) + lj * 16;
    static constexpr size_t GSTRIDE32 = (size_t)32 * K;
    static constexpr uint32_t SSTRIDE32 = 32 * (RSTRIDE * 2);

    // ldmatrix lane addressing
    const int sel = lid >> 3, lr = lid & 7;
    const int a_moff = (sel & 1) * 8, a_koff = (sel >> 1) * 8;   // A: m0k0,m8k0,m0k8,m8k8
    const int b_koff = (sel & 1) * 8, b_noff = (sel >> 1) * 8;   // B: n0k0,n0k8,n8k0,n8k8

    float c[4][4][4];
#pragma unroll
    for (int i = 0; i < 4; i++)
#pragma unroll
        for (int j = 0; j < 4; j++)
#pragma unroll
            for (int q = 0; q < 4; q++) c[i][j][q] = 0.f;

    // Prologue: fill STAGES-1 stages
#pragma unroll
    for (int s = 0; s < STAGES - 1; s++) {
        const uint32_t a_s = sb + s * STAGE_BYTES;
        const uint32_t b_s = a_s + A_BYTES;
        const int ko = s * TKT;
#pragma unroll
        for (int p = 0; p < 4; p++) {
            cp_async16(a_s + so + p * SSTRIDE32, gA + p * GSTRIDE32 + ko);
            cp_async16(b_s + so + p * SSTRIDE32, gB + p * GSTRIDE32 + ko);
        }
        CP_COMMIT();
    }

    int st = 0, nst = STAGES - 1;     // avoid %3 in the loop
    for (int kc = 0; kc < NK; kc++) {
        CP_WAIT(STAGES - 2);
        __syncthreads();
        const uint32_t a_s = sb + st * STAGE_BYTES;
        const uint32_t b_s = a_s + A_BYTES;

#pragma unroll
        for (int ks = 0; ks < 4; ks++) {
            const int kcol = ks * 16;
            uint32_t a[4][4], bb[2][4];
#pragma unroll
            for (int mf = 0; mf < 4; mf++) {
                const int arow = wm * 64 + mf * 16 + a_moff + lr;
                ldsm_x4(a[mf][0], a[mf][1], a[mf][2], a[mf][3],
                        a_s + (arow * RSTRIDE + kcol + a_koff) * 2);
            }
#pragma unroll
            for (int nf2 = 0; nf2 < 2; nf2++) {
                const int brow = wn * 32 + nf2 * 16 + b_noff + lr;
                ldsm_x4(bb[nf2][0], bb[nf2][1], bb[nf2][2], bb[nf2][3],
                        b_s + (brow * RSTRIDE + kcol + b_koff) * 2);
            }
#pragma unroll
            for (int mf = 0; mf < 4; mf++) {
#pragma unroll
                for (int nf = 0; nf < 4; nf++)
                    mma16816(c[mf][nf], a[mf],
                             bb[nf >> 1][(nf & 1) * 2], bb[nf >> 1][(nf & 1) * 2 + 1]);
            }
        }

        const int nk = kc + STAGES - 1;
        if (nk < NK) {
            const uint32_t na_s = sb + nst * STAGE_BYTES;
            const uint32_t nb_s = na_s + A_BYTES;
            const int ko = nk * TKT;
#pragma unroll
            for (int p = 0; p < 4; p++) {
                cp_async16(na_s + so + p * SSTRIDE32, gA + p * GSTRIDE32 + ko);
                cp_async16(nb_s + so + p * SSTRIDE32, gB + p * GSTRIDE32 + ko);
            }
        }
        CP_COMMIT();
        if (++st == STAGES) st = 0;
        if (++nst == STAGES) nst = 0;
    }

    // Epilogue: direct fp32 stores + bias
    const int qr = lid >> 2, qc = lid & 3;
#pragma unroll
    for (int mf = 0; mf < 4; mf++) {
        const int row = m0 + wm * 64 + mf * 16 + qr;
#pragma unroll
        for (int nf = 0; nf < 4; nf++) {
            const int col = n0 + wn * 32 + nf * 8 + qc * 2;
            const float2 b2 = *reinterpret_cast<const float2*>(bias + col);
            float2 v0 = make_float2(c[mf][nf][0] + b2.x, c[mf][nf][1] + b2.y);
            float2 v1 = make_float2(c[mf][nf][2] + b2.x, c[mf][nf][3] + b2.y);
            *reinterpret_cast<float2*>(out + (size_t)row * N + col) = v0;
            *reinterpret_cast<float2*>(out + (size_t)(row + 8) * N + col) = v1;
        }
    }
}

// ---------------------------------------------------------------------------
// Launch
// ---------------------------------------------------------------------------
extern "C" void kernel_launch(void* const* d_in, const int* in_sizes, int n_in,
                              void* d_out, int out_size) {
    (void)in_sizes; (void)n_in; (void)out_size;
    const float* x    = (const float*)d_in[0];
    const int*   qw   = (const int*)d_in[1];
    const float* sc   = (const float*)d_in[2];
    const int*   qz   = (const int*)d_in[3];
    const float* bias = (const float*)d_in[4];
    float* out = (float*)d_out;

    prep_kernel<<<PREP_BLOCKS, 256>>>(x, qw, sc, qz);

    cudaFuncSetAttribute(awq_gemm_kernel,
                         cudaFuncAttributeMaxDynamicSharedMemorySize, SMEM_TOTAL);
    awq_gemm_kernel<<<TILES_M * TILES_N, 256, SMEM_TOTAL>>>(bias, out);
}

// round 13
// speedup vs baseline: 1.2276x; 1.0864x over previous
#include <cuda_runtime.h>
#include <cuda_fp16.h>
#include <cstdint>

// ---------------------------------------------------------------------------
// Problem constants (fixed shapes)
// ---------------------------------------------------------------------------
static constexpr int M = 4096;
static constexpr int K = 4096;
static constexpr int N = 11008;
static constexpr int NP = N / 8;        // packed qweight cols
// GEMM tiling: CTA 128x128, 8 warps (2M x 4N), warp tile 64x32, TKT=64
static constexpr int TM = 128;
static constexpr int TN = 128;
static constexpr int TKT = 64;          // K elems per tile
static constexpr int STAGES = 3;
static constexpr int NK = K / TKT;      // 64 iterations
static constexpr int TILES_M = M / TM;  // 32
static constexpr int TILES_N = N / TN;  // 86

// SMEM stage: A[128][72] halfs then B[128][72] halfs
// 72-half rows = 36-word stride: 8-row ldmatrix footprints tile all 32 banks.
static constexpr int RSTRIDE = 72;
static constexpr int A_BYTES = TM * RSTRIDE * 2;        // 18432
static constexpr int STAGE_BYTES = 2 * A_BYTES;         // 36864
static constexpr int SMEM_TOTAL = STAGES * STAGE_BYTES; // 110592 (x2 CTAs/SM)

// Fused prep kernel partition
static constexpr int XBLOCKS = (M * K / 4) / 256;       // 16384 convert blocks
static constexpr int DQ_NB = N / 64;                    // 172
static constexpr int DQ_KB = K / 128;                   // 32
static constexpr int PREP_BLOCKS = XBLOCKS + DQ_NB * DQ_KB;

// ---------------------------------------------------------------------------
// Scratch (no allocation allowed anywhere)
// ---------------------------------------------------------------------------
__device__ __align__(256) __half g_xh[(size_t)M * K];   // x fp16 [M,K]
__device__ __align__(256) __half g_wh[(size_t)N * K];   // W fp16 [N,K] K-major

// ---------------------------------------------------------------------------
// PTX helpers (sm_80-level: assembles on plain sm_100 target)
// ---------------------------------------------------------------------------
__device__ __forceinline__ uint32_t smem_u32(const void* p) {
    uint32_t a;
    asm("{ .reg .u64 t; cvta.to.shared.u64 t, %1; cvt.u32.u64 %0, t; }"
        : "=r"(a) : "l"(p));
    return a;
}

__device__ __forceinline__ void cp_async16(uint32_t dst, const void* src) {
    asm volatile("cp.async.cg.shared.global [%0], [%1], 16;\n"
                 :: "r"(dst), "l"(src));
}
#define CP_COMMIT() asm volatile("cp.async.commit_group;" ::: "memory")
#define CP_WAIT(n)  asm volatile("cp.async.wait_group %0;" :: "n"(n) : "memory")

__device__ __forceinline__ void ldsm_x4(uint32_t& r0, uint32_t& r1,
                                        uint32_t& r2, uint32_t& r3, uint32_t addr) {
    asm volatile("ldmatrix.sync.aligned.m8n8.x4.shared.b16 {%0,%1,%2,%3}, [%4];"
                 : "=r"(r0), "=r"(r1), "=r"(r2), "=r"(r3) : "r"(addr));
}

__device__ __forceinline__ void mma16816(float* c, const uint32_t* a,
                                         uint32_t b0, uint32_t b1) {
    asm volatile(
        "mma.sync.aligned.m16n8k16.row.col.f32.f16.f16.f32 "
        "{%0,%1,%2,%3}, {%4,%5,%6,%7}, {%8,%9}, {%0,%1,%2,%3};"
        : "+f"(c[0]), "+f"(c[1]), "+f"(c[2]), "+f"(c[3])
        : "r"(a[0]), "r"(a[1]), "r"(a[2]), "r"(a[3]), "r"(b0), "r"(b1));
}

// ---------------------------------------------------------------------------
// Kernel 1 (fused prep): blocks [0, XBLOCKS) convert x fp32->fp16;
// blocks [XBLOCKS, ...) AWQ-dequant + transpose W -> g_wh[N][K] fp16.
// ---------------------------------------------------------------------------
__global__ void __launch_bounds__(256) prep_kernel(const float* __restrict__ x,
                                                   const int* __restrict__ qw,
                                                   const float* __restrict__ scales,
                                                   const int* __restrict__ qz) {
    const int t = threadIdx.x;
    if (blockIdx.x < XBLOCKS) {
        // ---- convert x ----
        const size_t i = (size_t)blockIdx.x * 256 + t;
        float4 f = reinterpret_cast<const float4*>(x)[i];
        reinterpret_cast<__half2*>(g_xh)[2 * i + 0] = __floats2half2_rn(f.x, f.y);
        reinterpret_cast<__half2*>(g_xh)[2 * i + 1] = __floats2half2_rn(f.z, f.w);
        return;
    }
    // ---- dequant W ----
    __shared__ __half wt[64][136];
    __shared__ float ss[64];
    __shared__ int   zz[8];

    const int bx = blockIdx.x - XBLOCKS;
    const int nt = (bx % DQ_NB) * 64;
    const int g  = bx / DQ_NB;           // group index (GROUP == 128 == K-tile)
    const int kt = g * 128;
    const int c0 = nt >> 3;

    if (t < 8)  zz[t] = qz[(size_t)g * NP + c0 + t];
    if (t < 64) ss[t] = scales[(size_t)g * N + nt + t];
    __syncthreads();

    const int klp   = t & 63;            // k-pair: k = 2*klp, 2*klp+1
    const int cbase = t >> 6;            // 0..3

#pragma unroll
    for (int p = 0; p < 2; p++) {
        const int cl = cbase + 4 * p;    // packed col 0..7
        const int zp = zz[cl];
        const int q0 = qw[(size_t)(kt + 2 * klp)     * NP + c0 + cl];
        const int q1 = qw[(size_t)(kt + 2 * klp + 1) * NP + c0 + cl];
#pragma unroll
        for (int i = 0; i < 8; i++) {
            // AWQ nibble shifts: 4 * [0,4,1,5,2,6,3,7]
            const int sh = ((i & 1) ? 16 : 0) + (i >> 1) * 4;
            const float s = ss[cl * 8 + i];
            const float z = (float)((zp >> sh) & 0xF);
            const float w0 = ((float)((q0 >> sh) & 0xF) - z) * s;
            const float w1 = ((float)((q1 >> sh) & 0xF) - z) * s;
            *reinterpret_cast<__half2*>(&wt[cl * 8 + i][2 * klp]) =
                __floats2half2_rn(w0, w1);
        }
    }
    __syncthreads();

#pragma unroll
    for (int p = 0; p < 4; p++) {
        const int idx = p * 256 + t;
        const int row = idx >> 4, ch = idx & 15;
        const uint4 v = *reinterpret_cast<const uint4*>(&wt[row][ch * 8]);
        *reinterpret_cast<uint4*>(&g_wh[(size_t)(nt + row) * K + kt + ch * 8]) = v;
    }
}

// ---------------------------------------------------------------------------
// Kernel 2: HMMA GEMM  out[M,N] = x @ W^T + bias
// R12 structure; the ONLY change: the 8 next-stage cp.asyncs are spread
// across the 4 ks compute sections (2 per section) instead of issued as a
// tail burst, smoothing LSU/smem-write pressure against ldsm reads.
// CTA 128x128, 8 warps (2x4), warp tile 64x32, TKT=64, 3 stages, 2 CTAs/SM.
// ---------------------------------------------------------------------------
__global__ void __launch_bounds__(256, 2) awq_gemm_kernel(const float* __restrict__ bias,
                                                          float* __restrict__ out) {
    extern __shared__ char smem[];
    const uint32_t sb = smem_u32(smem);
    const int t = threadIdx.x, wid = t >> 5, lid = t & 31;
    const int bm = blockIdx.x % TILES_M;       // M fastest: wave shares B-tiles in L2
    const int bn = blockIdx.x / TILES_M;
    const int m0 = bm * TM, n0 = bn * TN;
    const int wm = wid & 1, wn = wid >> 1;     // warp grid 2 (M) x 4 (N)

    // Hoisted cp.async addressing: 256 threads cover 32 rows/pass (8 x 16B
    // chunks per 128B row), 4 passes per operand.
    const int lrow = t >> 3, lj = t & 7;
    const __half* gA = g_xh + (size_t)(m0 + lrow) * K + lj * 8;
    const __half* gB = g_wh + (size_t)(n0 + lrow) * K + lj * 8;
    const uint32_t so = lrow * (RSTRIDE * 2) + lj * 16;
    static constexpr size_t GSTRIDE32 = (size_t)32 * K;
    static constexpr uint32_t SSTRIDE32 = 32 * (RSTRIDE * 2);

    // ldmatrix lane addressing
    const int sel = lid >> 3, lr = lid & 7;
    const int a_moff = (sel & 1) * 8, a_koff = (sel >> 1) * 8;   // A: m0k0,m8k0,m0k8,m8k8
    const int b_koff = (sel & 1) * 8, b_noff = (sel >> 1) * 8;   // B: n0k0,n0k8,n8k0,n8k8

    float c[4][4][4];
#pragma unroll
    for (int i = 0; i < 4; i++)
#pragma unroll
        for (int j = 0; j < 4; j++)
#pragma unroll
            for (int q = 0; q < 4; q++) c[i][j][q] = 0.f;

    // Prologue: fill STAGES-1 stages
#pragma unroll
    for (int s = 0; s < STAGES - 1; s++) {
        const uint32_t a_s = sb + s * STAGE_BYTES;
        const uint32_t b_s = a_s + A_BYTES;
        const int ko = s * TKT;
#pragma unroll
        for (int p = 0; p < 4; p++) {
            cp_async16(a_s + so + p * SSTRIDE32, gA + p * GSTRIDE32 + ko);
            cp_async16(b_s + so + p * SSTRIDE32, gB + p * GSTRIDE32 + ko);
        }
        CP_COMMIT();
    }

    int st = 0, nst = STAGES - 1;     // avoid %3 in the loop
    for (int kc = 0; kc < NK; kc++) {
        CP_WAIT(STAGES - 2);
        __syncthreads();
        const uint32_t a_s = sb + st * STAGE_BYTES;
        const uint32_t b_s = a_s + A_BYTES;

        // Next-stage prefetch targets (stage nst: last read at iter kc-1,
        // ordered by the barrier above -> safe to overwrite during compute).
        const int nk = kc + STAGES - 1;
        const bool pf = (nk < NK);
        const uint32_t na_s = sb + nst * STAGE_BYTES;
        const uint32_t nb_s = na_s + A_BYTES;
        const int ko = nk * TKT;

#pragma unroll
        for (int ks = 0; ks < 4; ks++) {
            const int kcol = ks * 16;
            uint32_t a[4][4], bb[2][4];
#pragma unroll
            for (int mf = 0; mf < 4; mf++) {
                const int arow = wm * 64 + mf * 16 + a_moff + lr;
                ldsm_x4(a[mf][0], a[mf][1], a[mf][2], a[mf][3],
                        a_s + (arow * RSTRIDE + kcol + a_koff) * 2);
            }
#pragma unroll
            for (int nf2 = 0; nf2 < 2; nf2++) {
                const int brow = wn * 32 + nf2 * 16 + b_noff + lr;
                ldsm_x4(bb[nf2][0], bb[nf2][1], bb[nf2][2], bb[nf2][3],
                        b_s + (brow * RSTRIDE + kcol + b_koff) * 2);
            }
            // 2 of the 8 prefetch chunks, issued in this section's MMA shadow
            if (pf) {
                cp_async16(na_s + so + ks * SSTRIDE32, gA + ks * GSTRIDE32 + ko);
                cp_async16(nb_s + so + ks * SSTRIDE32, gB + ks * GSTRIDE32 + ko);
            }
#pragma unroll
            for (int mf = 0; mf < 4; mf++) {
#pragma unroll
                for (int nf = 0; nf < 4; nf++)
                    mma16816(c[mf][nf], a[mf],
                             bb[nf >> 1][(nf & 1) * 2], bb[nf >> 1][(nf & 1) * 2 + 1]);
            }
        }

        CP_COMMIT();
        if (++st == STAGES) st = 0;
        if (++nst == STAGES) nst = 0;
    }

    // Epilogue: direct fp32 stores + bias
    const int qr = lid >> 2, qc = lid & 3;
#pragma unroll
    for (int mf = 0; mf < 4; mf++) {
        const int row = m0 + wm * 64 + mf * 16 + qr;
#pragma unroll
        for (int nf = 0; nf < 4; nf++) {
            const int col = n0 + wn * 32 + nf * 8 + qc * 2;
            const float2 b2 = *reinterpret_cast<const float2*>(bias + col);
            float2 v0 = make_float2(c[mf][nf][0] + b2.x, c[mf][nf][1] + b2.y);
            float2 v1 = make_float2(c[mf][nf][2] + b2.x, c[mf][nf][3] + b2.y);
            *reinterpret_cast<float2*>(out + (size_t)row * N + col) = v0;
            *reinterpret_cast<float2*>(out + (size_t)(row + 8) * N + col) = v1;
        }
    }
}

// ---------------------------------------------------------------------------
// Launch
// ---------------------------------------------------------------------------
extern "C" void kernel_launch(void* const* d_in, const int* in_sizes, int n_in,
                              void* d_out, int out_size) {
    (void)in_sizes; (void)n_in; (void)out_size;
    const float* x    = (const float*)d_in[0];
    const int*   qw   = (const int*)d_in[1];
    const float* sc   = (const float*)d_in[2];
    const int*   qz   = (const int*)d_in[3];
    const float* bias = (const float*)d_in[4];
    float* out = (float*)d_out;

    prep_kernel<<<PREP_BLOCKS, 256>>>(x, qw, sc, qz);

    cudaFuncSetAttribute(awq_gemm_kernel,
                         cudaFuncAttributeMaxDynamicSharedMemorySize, SMEM_TOTAL);
    awq_gemm_kernel<<<TILES_M * TILES_N, 256, SMEM_TOTAL>>>(bias, out);
}